// round 14
// baseline (speedup 1.0000x reference)
#include <cuda_runtime.h>
#include <math.h>
#include <stdint.h>

// ---------------- problem dims (fixed) ----------------
#define T_TOK  2048
#define HDIM   1024
#define IDIM   2816
#define NEXP   8
#define NASSIGN 4096
#define NTMAX  48
#define APAD   (NASSIGN + 128)
#define WELEMS (NEXP * HDIM * IDIM)

// ---------------- device scratch (static globals, allowed) ----------------
__device__ char  g_xq1[APAD * HDIM], g_xq2[APAD * HDIM];           // X digits
__device__ float g_sx[APAD];                                        // X row scales (s1)
__device__ float g_act[(size_t)APAD * IDIM];                        // SwiGLU out fp32
__device__ char  g_aq1[(size_t)APAD * IDIM], g_aq2[(size_t)APAD * IDIM];
__device__ float g_sa[APAD];                                        // act row scales (s1)
__device__ char  g_wgq1[WELEMS], g_wgq2[WELEMS];                    // Wg^T digits [E][I][H]
__device__ char  g_wuq1[WELEMS], g_wuq2[WELEMS];                    // Wu^T digits [E][I][H]
__device__ char  g_wdq1[WELEMS], g_wdq2[WELEMS];                    // Wd^T digits [E][H][I]
__device__ float g_bgmax[NEXP * IDIM];                              // colmax |Wg|
__device__ float g_bumax[NEXP * IDIM];
__device__ float g_bdmax[NEXP * HDIM];
__device__ float g_y[(size_t)APAD * HDIM];

__device__ int   g_perm_tok[NASSIGN];
__device__ float g_perm_w[NASSIGN];
__device__ int   g_pos[NASSIGN];
__device__ int   g_tok_eid[NASSIGN];
__device__ float g_tok_w[NASSIGN];
__device__ int   g_counts[NEXP];
__device__ int   g_off[NEXP + 1];
__device__ int   g_cursor[NEXP];
__device__ int   g_te[NTMAX], g_tr0[NTMAX];
__device__ int   g_nt;

// ---------------- PTX helpers (portable sm_80+ subset) ----------------
__device__ __forceinline__ uint32_t smem_u32(const void* p) {
    uint32_t a;
    asm("{ .reg .u64 t; cvta.to.shared.u64 t, %1; cvt.u32.u64 %0, t; }" : "=r"(a) : "l"(p));
    return a;
}
__device__ __forceinline__ void cpasync16(uint32_t dst, const void* src) {
    asm volatile("cp.async.cg.shared.global [%0], [%1], 16;" :: "r"(dst), "l"(src));
}
__device__ __forceinline__ void cp_commit() {
    asm volatile("cp.async.commit_group;" ::: "memory");
}
__device__ __forceinline__ void cp_wait1() {
    asm volatile("cp.async.wait_group 1;" ::: "memory");
}
__device__ __forceinline__ void ldsm4(uint32_t* r, uint32_t a) {
    asm volatile("ldmatrix.sync.aligned.m8n8.x4.shared.b16 {%0,%1,%2,%3}, [%4];"
                 : "=r"(r[0]), "=r"(r[1]), "=r"(r[2]), "=r"(r[3]) : "r"(a));
}
__device__ __forceinline__ void mma16832(int* c, const uint32_t* a, uint32_t b0, uint32_t b1) {
    asm volatile(
        "mma.sync.aligned.m16n8k32.row.col.s32.s8.s8.s32 "
        "{%0,%1,%2,%3}, {%4,%5,%6,%7}, {%8,%9}, {%0,%1,%2,%3};"
        : "+r"(c[0]), "+r"(c[1]), "+r"(c[2]), "+r"(c[3])
        : "r"(a[0]), "r"(a[1]), "r"(a[2]), "r"(a[3]), "r"(b0), "r"(b1));
}
// 64B int8 rows (KC=64), 4x16B chunks, XOR swizzle (validated geometry since R11)
__device__ __forceinline__ uint32_t sw64(int row, int ch) {
    return (uint32_t)(row * 64 + (((ch ^ ((row >> 1) & 3)) & 3) << 4));
}
__device__ __forceinline__ int q_rn(float v) {
    int q = __float2int_rn(v);
    return max(-127, min(127, q));
}
__device__ __forceinline__ void atomicMaxF(float* a, float v) {
    atomicMax((unsigned int*)a, __float_as_uint(v));   // v >= 0
}

// ---------------- small kernels ----------------
__global__ void k_init() {
    int i = threadIdx.x;
    if (i < NEXP) { g_counts[i] = 0; g_cursor[i] = 0; }
}

__global__ void k_zmax() {
    int i = blockIdx.x * 256 + threadIdx.x;
    if (i < NEXP * IDIM) g_bgmax[i] = 0.f;
    if (i < NEXP * IDIM) g_bumax[i] = 0.f;
    if (i < NEXP * HDIM) g_bdmax[i] = 0.f;
}

__global__ void k_router(const float* __restrict__ x, const float* __restrict__ gw,
                         float* __restrict__ out_logits, int write_logits) {
    int warp = threadIdx.x >> 5, lane = threadIdx.x & 31;
    int t = blockIdx.x * 8 + warp;
    const float* xt = x + (size_t)t * HDIM;
    float xr[32];
#pragma unroll
    for (int i = 0; i < 32; i++) xr[i] = xt[i * 32 + lane];
    float lg[NEXP];
#pragma unroll
    for (int e = 0; e < NEXP; e++) {
        const float* ge = gw + e * HDIM;
        float s = 0.f;
#pragma unroll
        for (int i = 0; i < 32; i++) s += xr[i] * ge[i * 32 + lane];
#pragma unroll
        for (int o = 16; o > 0; o >>= 1) s += __shfl_xor_sync(0xffffffffu, s, o);
        lg[e] = s;
    }
    if (lane == 0) {
        if (write_logits) {
#pragma unroll
            for (int e = 0; e < NEXP; e++) out_logits[t * NEXP + e] = lg[e];
        }
        int a = 0;
#pragma unroll
        for (int e = 1; e < NEXP; e++) if (lg[e] > lg[a]) a = e;
        int b = (a == 0) ? 1 : 0;
#pragma unroll
        for (int e = 0; e < NEXP; e++) if (e != a && lg[e] > lg[b]) b = e;
        float wa = 1.f / (1.f + expf(lg[b] - lg[a]));
        g_tok_eid[2 * t]     = a; g_tok_w[2 * t]     = wa;
        g_tok_eid[2 * t + 1] = b; g_tok_w[2 * t + 1] = 1.f - wa;
        atomicAdd(&g_counts[a], 1);
        atomicAdd(&g_counts[b], 1);
    }
}

__global__ void k_scan() {
    if (threadIdx.x != 0) return;
    int off = 0;
    for (int e = 0; e < NEXP; e++) { g_off[e] = off; g_cursor[e] = off; off += g_counts[e]; }
    g_off[NEXP] = off;
    int nt = 0;
    for (int e = 0; e < NEXP; e++)
        for (int r = 0; r < g_counts[e]; r += 128) { g_te[nt] = e; g_tr0[nt] = g_off[e] + r; nt++; }
    g_nt = nt;
}

__global__ void k_scatter() {
    int t = blockIdx.x * blockDim.x + threadIdx.x;
    if (t >= T_TOK) return;
#pragma unroll
    for (int k = 0; k < 2; k++) {
        int e = g_tok_eid[2 * t + k];
        int pos = atomicAdd(&g_cursor[e], 1);
        g_perm_tok[pos] = t;
        g_perm_w[pos]   = g_tok_w[2 * t + k];
        g_pos[2 * t + k] = pos;
    }
}

// gather token row -> per-row scale + 2-digit int8
__global__ void k_gatherquant(const float* __restrict__ x) {
    __shared__ float red[256];
    int pos = blockIdx.x, tid = threadIdx.x;
    int tok = g_perm_tok[pos];
    const float* xr = x + (size_t)tok * HDIM;
    float4 v = *(const float4*)(xr + tid * 4);
    float m = fmaxf(fmaxf(fabsf(v.x), fabsf(v.y)), fmaxf(fabsf(v.z), fabsf(v.w)));
    red[tid] = m;
    __syncthreads();
    for (int s = 128; s > 0; s >>= 1) {
        if (tid < s) red[tid] = fmaxf(red[tid], red[tid + s]);
        __syncthreads();
    }
    float s1 = fmaxf(red[0], 1e-20f) * (1.f / 127.f);
    float inv = 1.f / s1;
    float vv[4] = { v.x, v.y, v.z, v.w };
    char q1[4], q2[4];
#pragma unroll
    for (int j = 0; j < 4; j++) {
        int a = q_rn(vv[j] * inv);
        float r = vv[j] - (float)a * s1;
        int b = q_rn(r * 128.f * inv);
        q1[j] = (char)a; q2[j] = (char)b;
    }
    size_t o = (size_t)pos * HDIM + tid * 4;
    *(char4*)&g_xq1[o] = make_char4(q1[0], q1[1], q1[2], q1[3]);
    *(char4*)&g_xq2[o] = make_char4(q2[0], q2[1], q2[2], q2[3]);
    if (tid == 0) g_sx[pos] = s1;
}

// column max |W[e][k][n]| -> g_*max[e][n]
template<int SEL>
__global__ void k_colmax(const float* __restrict__ W) {
    constexpr int K = (SEL == 2) ? IDIM : HDIM;
    constexpr int N = (SEL == 2) ? HDIM : IDIM;
    float* mx = (SEL == 0) ? g_bgmax : (SEL == 1) ? g_bumax : g_bdmax;
    int n = blockIdx.x * 256 + threadIdx.x;
    int e = blockIdx.y;
    int ks = blockIdx.z, kn = (K + 7) / 8;
    int k0 = ks * kn, k1 = min(K, k0 + kn);
    const float* We = W + (size_t)e * K * N;
    float m = 0.f;
    for (int k = k0; k < k1; k++) m = fmaxf(m, fabsf(We[(size_t)k * N + n]));
    atomicMaxF(&mx[e * N + n], m);
}

// transpose + 2-digit quantize: W[e][K][N] fp32 -> q1,q2 [e][N][K] int8
template<int SEL>
__global__ void k_quantT(const float* __restrict__ W) {
    constexpr int K = (SEL == 2) ? IDIM : HDIM;
    constexpr int N = (SEL == 2) ? HDIM : IDIM;
    const float* mx = (SEL == 0) ? g_bgmax : (SEL == 1) ? g_bumax : g_bdmax;
    char* q1o = (SEL == 0) ? g_wgq1 : (SEL == 1) ? g_wuq1 : g_wdq1;
    char* q2o = (SEL == 0) ? g_wgq2 : (SEL == 1) ? g_wuq2 : g_wdq2;

    __shared__ float tile[32][33];
    int e = blockIdx.z;
    const float* We = W + (size_t)e * K * N;
    size_t ob = (size_t)e * K * N;
    int n0 = blockIdx.x * 32, k0 = blockIdx.y * 32;
    int tx = threadIdx.x, ty = threadIdx.y;
#pragma unroll
    for (int i = 0; i < 4; i++)
        tile[ty * 4 + i][tx] = We[(size_t)(k0 + ty * 4 + i) * N + n0 + tx];
    __syncthreads();
#pragma unroll
    for (int i = 0; i < 4; i++) {
        int r = ty * 4 + i;
        int n = n0 + r;
        float s1 = fmaxf(mx[e * N + n], 1e-20f) * (1.f / 127.f);
        float inv = 1.f / s1;
        float v = tile[tx][r];
        int a = q_rn(v * inv);
        float rr = v - (float)a * s1;
        int b = q_rn(rr * 128.f * inv);
        size_t o = ob + (size_t)n * K + k0 + tx;
        q1o[o] = (char)a;
        q2o[o] = (char)b;
    }
}

// ============ GEMM1 fused: G,U = X@Wg^T, X@Wu^T; act = silu(G)*U -> fp32 ============
// BM=128, BN=32 (G and U each), KC=64, 2-stage cp.async, 48KB static smem.
// int8 3-term: q1q1 + (q1q2 + q2q1)/128.  Warp tile: 32m x 16n of BOTH G and U.
#define F_A1 0
#define F_A2 8192
#define F_G1 16384
#define F_G2 18432
#define F_U1 20480
#define F_U2 22528
#define F_SZ 24576

__global__ __launch_bounds__(256)
void k_gemm1f() {
    constexpr int NCH = HDIM / 64;   // 16
    __shared__ __align__(16) char smem[2 * F_SZ];

    int bx = blockIdx.x;
    if (bx >= g_nt) return;
    int e = g_te[bx], row0 = g_tr0[bx], send = g_off[e + 1];
    int nblk = blockIdx.y * 32;
    int tid = threadIdx.x, lane = tid & 31, warp = tid >> 5;
    int wm = (warp >> 1) * 32, wn16 = (warp & 1) * 16;

    const char* pa1 = g_xq1 + (size_t)row0 * HDIM;
    const char* pa2 = g_xq2 + (size_t)row0 * HDIM;
    size_t eoff = ((size_t)e * IDIM + nblk) * HDIM;
    const char* pg1 = g_wgq1 + eoff;
    const char* pg2 = g_wgq2 + eoff;
    const char* pu1 = g_wuq1 + eoff;
    const char* pu2 = g_wuq2 + eoff;

    uint32_t sb = smem_u32(smem);

    auto issue = [&](int c) {
        if (c < NCH) {
            int k0 = c << 6;
            uint32_t b = sb + (uint32_t)(c & 1) * F_SZ;
#pragma unroll
            for (int r = 0; r < 2; r++) {          // A: 128 rows x 4 chunks, 2 digits
                int idx = r * 256 + tid;
                int row = idx >> 2, ch = idx & 3;
                uint32_t sw = sw64(row, ch);
                size_t go = (size_t)row * HDIM + k0 + ch * 16;
                cpasync16(b + F_A1 + sw, pa1 + go);
                cpasync16(b + F_A2 + sw, pa2 + go);
            }
#pragma unroll
            for (int r = 0; r < 2; r++) {          // B: 4 regions x 32 rows x 4 chunks
                int idx = r * 256 + tid;
                int reg = idx >> 7, within = idx & 127;
                int row = within >> 2, ch = within & 3;
                uint32_t sw = sw64(row, ch);
                size_t go = (size_t)row * HDIM + k0 + ch * 16;
                const char* src = (reg == 0) ? pg1 : (reg == 1) ? pg2 : (reg == 2) ? pu1 : pu2;
                cpasync16(b + F_G1 + reg * 2048 + sw, src + go);
            }
        }
        cp_commit();
    };

    issue(0);
    issue(1);

    int ag1[2][2][4], agx[2][2][4], au1[2][2][4], aux[2][2][4];
#pragma unroll
    for (int i = 0; i < 2; i++)
#pragma unroll
        for (int j = 0; j < 2; j++)
#pragma unroll
            for (int k = 0; k < 4; k++) {
                ag1[i][j][k] = 0; agx[i][j][k] = 0; au1[i][j][k] = 0; aux[i][j][k] = 0;
            }

    int lrow = lane & 15, lch = lane >> 4;

    for (int c = 0; c < NCH; c++) {
        cp_wait1();
        __syncthreads();
        uint32_t base = sb + (uint32_t)(c & 1) * F_SZ;
#pragma unroll
        for (int s = 0; s < 2; s++) {              // two k32 steps per chunk
            int ch = 2 * s + lch;
            uint32_t a1[2][4], a2[2][4];
#pragma unroll
            for (int mt = 0; mt < 2; mt++) {
                uint32_t sw = sw64(wm + mt * 16 + lrow, ch);
                ldsm4(a1[mt], base + F_A1 + sw);
                ldsm4(a2[mt], base + F_A2 + sw);
            }
            uint32_t swb = sw64(wn16 + lrow, ch);
            uint32_t bg1[4], bg2[4], bu1[4], bu2[4];
            ldsm4(bg1, base + F_G1 + swb);
            ldsm4(bg2, base + F_G2 + swb);
            ldsm4(bu1, base + F_U1 + swb);
            ldsm4(bu2, base + F_U2 + swb);
#pragma unroll
            for (int nh = 0; nh < 2; nh++) {
#pragma unroll
                for (int mt = 0; mt < 2; mt++) {
                    mma16832(ag1[mt][nh], a1[mt], bg1[nh], bg1[nh + 2]);
                    mma16832(agx[mt][nh], a1[mt], bg2[nh], bg2[nh + 2]);
                    mma16832(agx[mt][nh], a2[mt], bg1[nh], bg1[nh + 2]);
                    mma16832(au1[mt][nh], a1[mt], bu1[nh], bu1[nh + 2]);
                    mma16832(aux[mt][nh], a1[mt], bu2[nh], bu2[nh + 2]);
                    mma16832(aux[mt][nh], a2[mt], bu1[nh], bu1[nh + 2]);
                }
            }
        }
        __syncthreads();
        issue(c + 2);
    }

    // epilogue: dequant, SwiGLU, store fp32 act
    int r_off = lane >> 2, c_off = (lane & 3) * 2;
#pragma unroll
    for (int mt = 0; mt < 2; mt++) {
#pragma unroll
        for (int h = 0; h < 2; h++) {
            int row = row0 + wm + mt * 16 + r_off + h * 8;
            if (row >= send) continue;
            float sa = g_sx[row];
#pragma unroll
            for (int nh = 0; nh < 2; nh++) {
                int col = nblk + wn16 + nh * 8 + c_off;
                float sbg0 = g_bgmax[e * IDIM + col]     * (1.f / 127.f);
                float sbg1 = g_bgmax[e * IDIM + col + 1] * (1.f / 127.f);
                float sbu0 = g_bumax[e * IDIM + col]     * (1.f / 127.f);
                float sbu1 = g_bumax[e * IDIM + col + 1] * (1.f / 127.f);
                float g0 = sa * sbg0 * ((float)ag1[mt][nh][2 * h]     + (float)agx[mt][nh][2 * h]     * (1.f / 128.f));
                float g1 = sa * sbg1 * ((float)ag1[mt][nh][2 * h + 1] + (float)agx[mt][nh][2 * h + 1] * (1.f / 128.f));
                float u0 = sa * sbu0 * ((float)au1[mt][nh][2 * h]     + (float)aux[mt][nh][2 * h]     * (1.f / 128.f));
                float u1 = sa * sbu1 * ((float)au1[mt][nh][2 * h + 1] + (float)aux[mt][nh][2 * h + 1] * (1.f / 128.f));
                float2 o;
                o.x = g0 * u0 / (1.f + __expf(-g0));
                o.y = g1 * u1 / (1.f + __expf(-g1));
                *(float2*)&g_act[(size_t)row * IDIM + col] = o;
            }
        }
    }
}

// act fp32 -> per-row scale + 2-digit int8
__global__ void k_actquant() {
    __shared__ float red[256];
    int pos = blockIdx.x, tid = threadIdx.x;
    const float* ar = g_act + (size_t)pos * IDIM;
    float m = 0.f;
    for (int i = tid; i < IDIM; i += 256) m = fmaxf(m, fabsf(ar[i]));
    red[tid] = m;
    __syncthreads();
    for (int s = 128; s > 0; s >>= 1) {
        if (tid < s) red[tid] = fmaxf(red[tid], red[tid + s]);
        __syncthreads();
    }
    float s1 = fmaxf(red[0], 1e-20f) * (1.f / 127.f);
    float inv = 1.f / s1;
    size_t base = (size_t)pos * IDIM;
    for (int i = tid; i < IDIM; i += 256) {
        float v = ar[i];
        int a = q_rn(v * inv);
        float r = v - (float)a * s1;
        int b = q_rn(r * 128.f * inv);
        g_aq1[base + i] = (char)a;
        g_aq2[base + i] = (char)b;
    }
    if (tid == 0) g_sa[pos] = s1;
}

// ============ GEMM2: Y = act@Wd^T  (BM=128, BN=64, KC=64, 2-stage, 48KB) ============
#define D_A1 0
#define D_A2 8192
#define D_B1 16384
#define D_B2 20480
#define D_SZ 24576

__global__ __launch_bounds__(256)
void k_gemm2() {
    constexpr int NCH = IDIM / 64;   // 44
    __shared__ __align__(16) char smem[2 * D_SZ];

    int bx = blockIdx.x;
    if (bx >= g_nt) return;
    int e = g_te[bx], row0 = g_tr0[bx], send = g_off[e + 1];
    int nblk = blockIdx.y * 64;
    int tid = threadIdx.x, lane = tid & 31, warp = tid >> 5;
    int wm = (warp >> 1) * 32, wn = (warp & 1) * 32;

    const char* pa1 = g_aq1 + (size_t)row0 * IDIM;
    const char* pa2 = g_aq2 + (size_t)row0 * IDIM;
    size_t eoff = ((size_t)e * HDIM + nblk) * IDIM;
    const char* pb1 = g_wdq1 + eoff;
    const char* pb2 = g_wdq2 + eoff;

    uint32_t sb = smem_u32(smem);

    auto issue = [&](int c) {
        if (c < NCH) {
            int k0 = c << 6;
            uint32_t b = sb + (uint32_t)(c & 1) * D_SZ;
#pragma unroll
            for (int r = 0; r < 2; r++) {          // A: 128 rows x 4 chunks, 2 digits
                int idx = r * 256 + tid;
                int row = idx >> 2, ch = idx & 3;
                uint32_t sw = sw64(row, ch);
                size_t go = (size_t)row * IDIM + k0 + ch * 16;
                cpasync16(b + D_A1 + sw, pa1 + go);
                cpasync16(b + D_A2 + sw, pa2 + go);
            }
            {                                       // B: 64 rows x 4 chunks, 2 digits
                int row = tid >> 2, ch = tid & 3;
                uint32_t sw = sw64(row, ch);
                size_t go = (size_t)row * IDIM + k0 + ch * 16;
                cpasync16(b + D_B1 + sw, pb1 + go);
                cpasync16(b + D_B2 + sw, pb2 + go);
            }
        }
        cp_commit();
    };

    issue(0);
    issue(1);

    int a11[2][4][4], axx[2][4][4];
#pragma unroll
    for (int i = 0; i < 2; i++)
#pragma unroll
        for (int j = 0; j < 4; j++)
#pragma unroll
            for (int k = 0; k < 4; k++) { a11[i][j][k] = 0; axx[i][j][k] = 0; }

    int lrow = lane & 15, lch = lane >> 4;

    for (int c = 0; c < NCH; c++) {
        cp_wait1();
        __syncthreads();
        uint32_t base = sb + (uint32_t)(c & 1) * D_SZ;
#pragma unroll
        for (int s = 0; s < 2; s++) {
            int ch = 2 * s + lch;
            uint32_t a1[2][4], a2[2][4];
#pragma unroll
            for (int mt = 0; mt < 2; mt++) {
                uint32_t sw = sw64(wm + mt * 16 + lrow, ch);
                ldsm4(a1[mt], base + D_A1 + sw);
                ldsm4(a2[mt], base + D_A2 + sw);
            }
#pragma unroll
            for (int p = 0; p < 2; p++) {
                uint32_t sw = sw64(wn + p * 16 + lrow, ch);
                uint32_t b1[4], b2[4];
                ldsm4(b1, base + D_B1 + sw);
                ldsm4(b2, base + D_B2 + sw);
#pragma unroll
                for (int nh = 0; nh < 2; nh++) {
                    int nt = 2 * p + nh;
#pragma unroll
                    for (int mt = 0; mt < 2; mt++) {
                        mma16832(a11[mt][nt], a1[mt], b1[nh], b1[nh + 2]);
                        mma16832(axx[mt][nt], a1[mt], b2[nh], b2[nh + 2]);
                        mma16832(axx[mt][nt], a2[mt], b1[nh], b1[nh + 2]);
                    }
                }
            }
        }
        __syncthreads();
        issue(c + 2);
    }

    int r_off = lane >> 2, c_off = (lane & 3) * 2;
#pragma unroll
    for (int mt = 0; mt < 2; mt++) {
#pragma unroll
        for (int h = 0; h < 2; h++) {
            int row = row0 + wm + mt * 16 + r_off + h * 8;
            if (row >= send) continue;
            float sa = g_sa[row];
#pragma unroll
            for (int nt = 0; nt < 4; nt++) {
                int col = nblk + wn + nt * 8 + c_off;
                float sb0 = g_bdmax[e * HDIM + col]     * (1.f / 127.f);
                float sb1 = g_bdmax[e * HDIM + col + 1] * (1.f / 127.f);
                float2 o;
                o.x = sa * sb0 * ((float)a11[mt][nt][2 * h]     + (float)axx[mt][nt][2 * h]     * (1.f / 128.f));
                o.y = sa * sb1 * ((float)a11[mt][nt][2 * h + 1] + (float)axx[mt][nt][2 * h + 1] * (1.f / 128.f));
                *(float2*)&g_y[(size_t)row * HDIM + col] = o;
            }
        }
    }
}

// ---------------- combine: out[t] = w0*y[p0] + w1*y[p1] ----------------
__global__ void k_combine(float* __restrict__ out) {
    int t = blockIdx.x;
    int h = threadIdx.x * 4;
    int p0 = g_pos[2 * t], p1 = g_pos[2 * t + 1];
    float w0 = g_perm_w[p0], w1 = g_perm_w[p1];
    float4 a = *(const float4*)&g_y[(size_t)p0 * HDIM + h];
    float4 b = *(const float4*)&g_y[(size_t)p1 * HDIM + h];
    float4 o;
    o.x = w0 * a.x + w1 * b.x;
    o.y = w0 * a.y + w1 * b.y;
    o.z = w0 * a.z + w1 * b.z;
    o.w = w0 * a.w + w1 * b.w;
    *(float4*)(out + (size_t)t * HDIM + h) = o;
}

// ---------------- launcher (no device-global symbols passed as args) ----------------
extern "C" void kernel_launch(void* const* d_in, const int* in_sizes, int n_in,
                              void* d_out, int out_size) {
    (void)in_sizes; (void)n_in;
    const float* x  = (const float*)d_in[0];
    const float* gw = (const float*)d_in[1];
    const float* wg = (const float*)d_in[2];
    const float* wu = (const float*)d_in[3];
    const float* wd = (const float*)d_in[4];
    float* out = (float*)d_out;

    int write_logits = (out_size >= T_TOK * HDIM + T_TOK * NEXP) ? 1 : 0;

    k_init<<<1, 32>>>();
    k_zmax<<<(NEXP * IDIM + 255) / 256, 256>>>();
    k_router<<<T_TOK / 8, 256>>>(x, gw, out + (size_t)T_TOK * HDIM, write_logits);
    k_scan<<<1, 1>>>();
    k_scatter<<<T_TOK / 256, 256>>>();
    k_gatherquant<<<NASSIGN, 256>>>(x);
    // weight prep: column max then transpose+quantize to 2-digit int8
    k_colmax<0><<<dim3(IDIM / 256, NEXP, 8), 256>>>(wg);
    k_colmax<1><<<dim3(IDIM / 256, NEXP, 8), 256>>>(wu);
    k_colmax<2><<<dim3(HDIM / 256, NEXP, 8), 256>>>(wd);
    k_quantT<0><<<dim3(IDIM / 32, HDIM / 32, NEXP), dim3(32, 8)>>>(wg);
    k_quantT<1><<<dim3(IDIM / 32, HDIM / 32, NEXP), dim3(32, 8)>>>(wu);
    k_quantT<2><<<dim3(HDIM / 32, IDIM / 32, NEXP), dim3(32, 8)>>>(wd);
    // int8 grouped GEMMs (3-term, 2x MACs/instr vs bf16)
    k_gemm1f<<<dim3(40, IDIM / 32), 256>>>();
    k_actquant<<<NASSIGN, 256>>>();
    k_gemm2<<<dim3(40, HDIM / 64), 256>>>();
    k_combine<<<T_TOK, 256>>>(out);
}

// round 15
// speedup vs baseline: 2.2382x; 2.2382x over previous
#include <cuda_runtime.h>
#include <cuda_bf16.h>
#include <math.h>
#include <stdint.h>

// ---------------- problem dims (fixed) ----------------
#define T_TOK  2048
#define HDIM   1024
#define IDIM   2816
#define NEXP   8
#define NASSIGN 4096
#define NTMAX  48
#define APAD   (NASSIGN + 128)
#define WELEMS (NEXP * HDIM * IDIM)

// ---------------- device scratch (static globals, allowed) ----------------
__device__ __nv_bfloat16 g_xg_hi[APAD * HDIM];
__device__ __nv_bfloat16 g_xg_lo[APAD * HDIM];
__device__ __nv_bfloat16 g_act_hi[(size_t)APAD * IDIM];
__device__ __nv_bfloat16 g_act_lo[(size_t)APAD * IDIM];
__device__ float g_y[(size_t)APAD * HDIM];
__device__ __nv_bfloat16 g_wgt_hi[WELEMS], g_wgt_lo[WELEMS];   // w_gate^T [E][I][H]
__device__ __nv_bfloat16 g_wut_hi[WELEMS], g_wut_lo[WELEMS];   // w_up^T   [E][I][H]
__device__ __nv_bfloat16 g_wdt_hi[WELEMS], g_wdt_lo[WELEMS];   // w_down^T [E][H][I]

__device__ int   g_perm_tok[NASSIGN];
__device__ float g_perm_w[NASSIGN];
__device__ int   g_pos[NASSIGN];
__device__ int   g_tok_eid[NASSIGN];
__device__ float g_tok_w[NASSIGN];
__device__ int   g_counts[NEXP];
__device__ int   g_off[NEXP + 1];
__device__ int   g_cursor[NEXP];
__device__ int   g_te[NTMAX], g_tr0[NTMAX];
__device__ int   g_nt;

// ---------------- PTX helpers (portable sm_80+ subset) ----------------
__device__ __forceinline__ uint32_t smem_u32(const void* p) {
    uint32_t a;
    asm("{ .reg .u64 t; cvta.to.shared.u64 t, %1; cvt.u32.u64 %0, t; }" : "=r"(a) : "l"(p));
    return a;
}
__device__ __forceinline__ void cpasync16(uint32_t dst, const void* src) {
    asm volatile("cp.async.cg.shared.global [%0], [%1], 16;" :: "r"(dst), "l"(src));
}
__device__ __forceinline__ void cp_commit() {
    asm volatile("cp.async.commit_group;" ::: "memory");
}
__device__ __forceinline__ void cp_wait1() {
    asm volatile("cp.async.wait_group 1;" ::: "memory");
}
__device__ __forceinline__ void ldsm4(uint32_t* r, uint32_t a) {
    asm volatile("ldmatrix.sync.aligned.m8n8.x4.shared.b16 {%0,%1,%2,%3}, [%4];"
                 : "=r"(r[0]), "=r"(r[1]), "=r"(r[2]), "=r"(r[3]) : "r"(a));
}
__device__ __forceinline__ void mma16816(float* c, const uint32_t* a, uint32_t b0, uint32_t b1) {
    asm volatile(
        "mma.sync.aligned.m16n8k16.row.col.f32.bf16.bf16.f32 "
        "{%0,%1,%2,%3}, {%4,%5,%6,%7}, {%8,%9}, {%0,%1,%2,%3};"
        : "+f"(c[0]), "+f"(c[1]), "+f"(c[2]), "+f"(c[3])
        : "r"(a[0]), "r"(a[1]), "r"(a[2]), "r"(a[3]), "r"(b0), "r"(b1));
}
// 64B rows (KC=32 bf16), 4x16B chunks, XOR swizzle ch ^= (row>>1)&3 (R11-proven)
__device__ __forceinline__ uint32_t swz64(int row, int ch) {
    return (uint32_t)(row * 64 + (((ch ^ ((row >> 1) & 3)) & 3) << 4));
}

// ---------------- small kernels ----------------
__global__ void k_init() {
    int i = threadIdx.x;
    if (i < NEXP) { g_counts[i] = 0; g_cursor[i] = 0; }
}

__global__ void k_router(const float* __restrict__ x, const float* __restrict__ gw,
                         float* __restrict__ out_logits, int write_logits) {
    int warp = threadIdx.x >> 5, lane = threadIdx.x & 31;
    int t = blockIdx.x * 8 + warp;
    const float* xt = x + (size_t)t * HDIM;
    float xr[32];
#pragma unroll
    for (int i = 0; i < 32; i++) xr[i] = xt[i * 32 + lane];
    float lg[NEXP];
#pragma unroll
    for (int e = 0; e < NEXP; e++) {
        const float* ge = gw + e * HDIM;
        float s = 0.f;
#pragma unroll
        for (int i = 0; i < 32; i++) s += xr[i] * ge[i * 32 + lane];
#pragma unroll
        for (int o = 16; o > 0; o >>= 1) s += __shfl_xor_sync(0xffffffffu, s, o);
        lg[e] = s;
    }
    if (lane == 0) {
        if (write_logits) {
#pragma unroll
            for (int e = 0; e < NEXP; e++) out_logits[t * NEXP + e] = lg[e];
        }
        int a = 0;
#pragma unroll
        for (int e = 1; e < NEXP; e++) if (lg[e] > lg[a]) a = e;
        int b = (a == 0) ? 1 : 0;
#pragma unroll
        for (int e = 0; e < NEXP; e++) if (e != a && lg[e] > lg[b]) b = e;
        float wa = 1.f / (1.f + expf(lg[b] - lg[a]));
        g_tok_eid[2 * t]     = a; g_tok_w[2 * t]     = wa;
        g_tok_eid[2 * t + 1] = b; g_tok_w[2 * t + 1] = 1.f - wa;
        atomicAdd(&g_counts[a], 1);
        atomicAdd(&g_counts[b], 1);
    }
}

__global__ void k_scan() {
    if (threadIdx.x != 0) return;
    int off = 0;
    for (int e = 0; e < NEXP; e++) { g_off[e] = off; g_cursor[e] = off; off += g_counts[e]; }
    g_off[NEXP] = off;
    int nt = 0;
    for (int e = 0; e < NEXP; e++)
        for (int r = 0; r < g_counts[e]; r += 128) { g_te[nt] = e; g_tr0[nt] = g_off[e] + r; nt++; }
    g_nt = nt;
}

__global__ void k_scatter() {
    int t = blockIdx.x * blockDim.x + threadIdx.x;
    if (t >= T_TOK) return;
#pragma unroll
    for (int k = 0; k < 2; k++) {
        int e = g_tok_eid[2 * t + k];
        int pos = atomicAdd(&g_cursor[e], 1);
        g_perm_tok[pos] = t;
        g_perm_w[pos]   = g_tok_w[2 * t + k];
        g_pos[2 * t + k] = pos;
    }
}

__global__ void k_gather(const float* __restrict__ x) {
    int pos = blockIdx.x;
    int tok = g_perm_tok[pos];
    int i = threadIdx.x * 4;
    float4 v = *(const float4*)(x + (size_t)tok * HDIM + i);
    size_t o = (size_t)pos * HDIM + i;
    float vv[4] = { v.x, v.y, v.z, v.w };
#pragma unroll
    for (int j = 0; j < 4; j++) {
        __nv_bfloat16 h = __float2bfloat16(vv[j]);
        g_xg_hi[o + j] = h;
        g_xg_lo[o + j] = __float2bfloat16(vv[j] - __bfloat162float(h));
    }
}

// transpose W[e][K][N] fp32 -> hi/lo bf16 [e][N][K] (globals only in device code)
template<int SEL>
__global__ void k_transpose(const float* __restrict__ W) {
    constexpr int K = (SEL == 2) ? IDIM : HDIM;
    constexpr int N = (SEL == 2) ? HDIM : IDIM;
    __nv_bfloat16* hi = (SEL == 0) ? g_wgt_hi : (SEL == 1) ? g_wut_hi : g_wdt_hi;
    __nv_bfloat16* lo = (SEL == 0) ? g_wgt_lo : (SEL == 1) ? g_wut_lo : g_wdt_lo;

    __shared__ float tile[32][33];
    int e = blockIdx.z;
    const float* We = W + (size_t)e * K * N;
    size_t ob = (size_t)e * K * N;
    int n0 = blockIdx.x * 32, k0 = blockIdx.y * 32;
    int tx = threadIdx.x, ty = threadIdx.y;
#pragma unroll
    for (int i = 0; i < 4; i++)
        tile[ty * 4 + i][tx] = We[(size_t)(k0 + ty * 4 + i) * N + n0 + tx];
    __syncthreads();
#pragma unroll
    for (int i = 0; i < 4; i++) {
        int r = ty * 4 + i;
        float v = tile[tx][r];
        __nv_bfloat16 h = __float2bfloat16(v);
        size_t o = ob + (size_t)(n0 + r) * K + k0 + tx;
        hi[o] = h;
        lo[o] = __float2bfloat16(v - __bfloat162float(h));
    }
}

// ======= GEMM1 fused: G,U = X@Wg^T,X@Wu^T shared A tile; SwiGLU epilogue ==========
// BM=128, BN=32 (G) + 32 (U), KC=32, 2-stage cp.async, 48KB static smem (R11 geometry).
// stage (24KB): [Ah 8K | Al 8K | Gh 2K | Gl 2K | Uh 2K | Ul 2K]
#define F_A1 0
#define F_A2 8192
#define F_G1 16384
#define F_G2 18432
#define F_U1 20480
#define F_U2 22528
#define F_SZ 24576

__global__ __launch_bounds__(256)
void k_gemm1f() {
    constexpr int NCH = HDIM / 32;   // 32 chunks
    __shared__ __align__(16) char smem[2 * F_SZ];

    int bx = blockIdx.x;
    if (bx >= g_nt) return;
    int e = g_te[bx], row0 = g_tr0[bx], send = g_off[e + 1];
    int nblk = blockIdx.y * 32;      // 32 cols of BOTH G and U
    int tid = threadIdx.x, lane = tid & 31, warp = tid >> 5;
    int wm = (warp >> 1) * 32, wn16 = (warp & 1) * 16;   // 4M x 2N warps

    const __nv_bfloat16* pa_h = g_xg_hi + (size_t)row0 * HDIM;
    const __nv_bfloat16* pa_l = g_xg_lo + (size_t)row0 * HDIM;
    size_t eoff = ((size_t)e * IDIM + nblk) * HDIM;
    const __nv_bfloat16* pg_h = g_wgt_hi + eoff;
    const __nv_bfloat16* pg_l = g_wgt_lo + eoff;
    const __nv_bfloat16* pu_h = g_wut_hi + eoff;
    const __nv_bfloat16* pu_l = g_wut_lo + eoff;

    uint32_t sb = smem_u32(smem);

    auto issue = [&](int c) {
        if (c < NCH) {
            int k0 = c << 5;
            uint32_t b = sb + (uint32_t)(c & 1) * F_SZ;
#pragma unroll
            for (int r = 0; r < 2; r++) {          // A: 128 rows x 4 chunks, hi+lo
                int idx = r * 256 + tid;
                int row = idx >> 2, ch = idx & 3;
                uint32_t sw = swz64(row, ch);
                size_t go = (size_t)row * HDIM + k0 + ch * 8;
                cpasync16(b + F_A1 + sw, pa_h + go);
                cpasync16(b + F_A2 + sw, pa_l + go);
            }
#pragma unroll
            for (int r = 0; r < 2; r++) {          // B: 4 regions x 32 rows x 4 chunks
                int idx = r * 256 + tid;
                int reg = idx >> 7, within = idx & 127;
                int row = within >> 2, ch = within & 3;
                uint32_t sw = swz64(row, ch);
                size_t go = (size_t)row * HDIM + k0 + ch * 8;
                const __nv_bfloat16* src =
                    (reg == 0) ? pg_h : (reg == 1) ? pg_l : (reg == 2) ? pu_h : pu_l;
                cpasync16(b + F_G1 + reg * 2048 + sw, src + go);
            }
        }
        cp_commit();
    };

    issue(0);
    issue(1);

    float ag[2][2][4], au[2][2][4];
#pragma unroll
    for (int i = 0; i < 2; i++)
#pragma unroll
        for (int j = 0; j < 2; j++)
#pragma unroll
            for (int k = 0; k < 4; k++) { ag[i][j][k] = 0.f; au[i][j][k] = 0.f; }

    int lrow = lane & 15, lch = lane >> 4;

    for (int c = 0; c < NCH; c++) {
        cp_wait1();
        __syncthreads();
        uint32_t base = sb + (uint32_t)(c & 1) * F_SZ;
#pragma unroll
        for (int s = 0; s < 2; s++) {              // two k16 steps per 32-chunk
            int ch = 2 * s + lch;
            uint32_t ah[2][4], al[2][4];
#pragma unroll
            for (int mt = 0; mt < 2; mt++) {
                uint32_t sw = swz64(wm + mt * 16 + lrow, ch);
                ldsm4(ah[mt], base + F_A1 + sw);
                ldsm4(al[mt], base + F_A2 + sw);
            }
            uint32_t swb = swz64(wn16 + lrow, ch);
            uint32_t bgh[4], bgl[4], buh[4], bul[4];
            ldsm4(bgh, base + F_G1 + swb);
            ldsm4(bgl, base + F_G2 + swb);
            ldsm4(buh, base + F_U1 + swb);
            ldsm4(bul, base + F_U2 + swb);
#pragma unroll
            for (int nh = 0; nh < 2; nh++) {
#pragma unroll
                for (int mt = 0; mt < 2; mt++) {
                    mma16816(ag[mt][nh], ah[mt], bgh[nh], bgh[nh + 2]);
                    mma16816(ag[mt][nh], al[mt], bgh[nh], bgh[nh + 2]);
                    mma16816(ag[mt][nh], ah[mt], bgl[nh], bgl[nh + 2]);
                    mma16816(au[mt][nh], ah[mt], buh[nh], buh[nh + 2]);
                    mma16816(au[mt][nh], al[mt], buh[nh], buh[nh + 2]);
                    mma16816(au[mt][nh], ah[mt], bul[nh], bul[nh + 2]);
                }
            }
        }
        __syncthreads();
        issue(c + 2);
    }

    // fused SwiGLU epilogue: act = silu(g)*u -> hi/lo bf16
    int r_off = lane >> 2, c_off = (lane & 3) * 2;
#pragma unroll
    for (int mt = 0; mt < 2; mt++) {
#pragma unroll
        for (int h = 0; h < 2; h++) {
            int row = row0 + wm + mt * 16 + r_off + h * 8;
            if (row >= send) continue;
#pragma unroll
            for (int nh = 0; nh < 2; nh++) {
                float g0 = ag[mt][nh][2 * h + 0], g1 = ag[mt][nh][2 * h + 1];
                float u0 = au[mt][nh][2 * h + 0], u1 = au[mt][nh][2 * h + 1];
                float a0 = g0 * u0 / (1.f + __expf(-g0));
                float a1 = g1 * u1 / (1.f + __expf(-g1));
                __nv_bfloat16 h0 = __float2bfloat16(a0);
                __nv_bfloat16 h1 = __float2bfloat16(a1);
                __nv_bfloat16 l0 = __float2bfloat16(a0 - __bfloat162float(h0));
                __nv_bfloat16 l1 = __float2bfloat16(a1 - __bfloat162float(h1));
                size_t o = (size_t)row * IDIM + nblk + wn16 + nh * 8 + c_off;
                *reinterpret_cast<__nv_bfloat162*>(&g_act_hi[o]) = __nv_bfloat162(h0, h1);
                *reinterpret_cast<__nv_bfloat162*>(&g_act_lo[o]) = __nv_bfloat162(l0, l1);
            }
        }
    }
}

// ======= GEMM2: Y = act@Wd^T  (R11 SEL=2 kernel, unchanged geometry) ==============
// BM=128, BN=64, KC=32, 2-stage, 48KB static. stage: [Ah 8K | Al 8K | Bh 4K | Bl 4K]
#define ST_AH 0
#define ST_AL 8192
#define ST_BH 16384
#define ST_BL 20480
#define ST_SZ 24576

__global__ __launch_bounds__(256)
void k_gemm2() {
    constexpr int Kd = IDIM, Nd = HDIM;
    constexpr int NCH = Kd / 32;
    __shared__ __align__(16) char smem[2 * ST_SZ];

    int bx = blockIdx.x;
    if (bx >= g_nt) return;
    int e = g_te[bx], row0 = g_tr0[bx], send = g_off[e + 1];
    int nblk = blockIdx.y * 64;
    int tid = threadIdx.x, lane = tid & 31, warp = tid >> 5;
    int wm = (warp >> 1) * 32, wn = (warp & 1) * 32;

    const __nv_bfloat16* pa_h = g_act_hi + (size_t)row0 * Kd;
    const __nv_bfloat16* pa_l = g_act_lo + (size_t)row0 * Kd;
    const __nv_bfloat16* pb_h = g_wdt_hi + ((size_t)e * Nd + nblk) * Kd;
    const __nv_bfloat16* pb_l = g_wdt_lo + ((size_t)e * Nd + nblk) * Kd;

    uint32_t sb = smem_u32(smem);

    auto issue = [&](int c) {
        if (c < NCH) {
            int k0 = c << 5;
            uint32_t b = sb + (uint32_t)(c & 1) * ST_SZ;
#pragma unroll
            for (int r = 0; r < 2; r++) {
                int idx = r * 256 + tid;
                int row = idx >> 2, ch = idx & 3;
                uint32_t sw = swz64(row, ch);
                size_t go = (size_t)row * Kd + k0 + ch * 8;
                cpasync16(b + ST_AH + sw, pa_h + go);
                cpasync16(b + ST_AL + sw, pa_l + go);
            }
            {
                int row = tid >> 2, ch = tid & 3;
                uint32_t sw = swz64(row, ch);
                size_t go = (size_t)row * Kd + k0 + ch * 8;
                cpasync16(b + ST_BH + sw, pb_h + go);
                cpasync16(b + ST_BL + sw, pb_l + go);
            }
        }
        cp_commit();
    };

    issue(0);
    issue(1);

    float acc[2][4][4];
#pragma unroll
    for (int i = 0; i < 2; i++)
#pragma unroll
        for (int j = 0; j < 4; j++)
#pragma unroll
            for (int k = 0; k < 4; k++) acc[i][j][k] = 0.f;

    int lrow = lane & 15, lch = lane >> 4;

    for (int c = 0; c < NCH; c++) {
        cp_wait1();
        __syncthreads();
        uint32_t base = sb + (uint32_t)(c & 1) * ST_SZ;
#pragma unroll
        for (int s = 0; s < 2; s++) {
            int ch = 2 * s + lch;
            uint32_t ah[2][4], al[2][4];
#pragma unroll
            for (int mt = 0; mt < 2; mt++) {
                uint32_t sw = swz64(wm + mt * 16 + lrow, ch);
                ldsm4(ah[mt], base + ST_AH + sw);
                ldsm4(al[mt], base + ST_AL + sw);
            }
#pragma unroll
            for (int p = 0; p < 2; p++) {
                uint32_t sw = swz64(wn + p * 16 + lrow, ch);
                uint32_t bh[4], bl[4];
                ldsm4(bh, base + ST_BH + sw);
                ldsm4(bl, base + ST_BL + sw);
#pragma unroll
                for (int mt = 0; mt < 2; mt++) {
                    mma16816(acc[mt][2 * p],     ah[mt], bh[0], bh[2]);
                    mma16816(acc[mt][2 * p],     al[mt], bh[0], bh[2]);
                    mma16816(acc[mt][2 * p],     ah[mt], bl[0], bl[2]);
                    mma16816(acc[mt][2 * p + 1], ah[mt], bh[1], bh[3]);
                    mma16816(acc[mt][2 * p + 1], al[mt], bh[1], bh[3]);
                    mma16816(acc[mt][2 * p + 1], ah[mt], bl[1], bl[3]);
                }
            }
        }
        __syncthreads();
        issue(c + 2);
    }

    int r_off = lane >> 2, c_off = (lane & 3) * 2;
#pragma unroll
    for (int mt = 0; mt < 2; mt++) {
#pragma unroll
        for (int h = 0; h < 2; h++) {
            int row = row0 + wm + mt * 16 + r_off + h * 8;
            if (row >= send) continue;
            float* crow = g_y + (size_t)row * Nd + nblk + wn + c_off;
#pragma unroll
            for (int nt = 0; nt < 4; nt++) {
                crow[nt * 8 + 0] = acc[mt][nt][2 * h + 0];
                crow[nt * 8 + 1] = acc[mt][nt][2 * h + 1];
            }
        }
    }
}

// ---------------- combine: out[t] = w0*y[p0] + w1*y[p1] ----------------
__global__ void k_combine(float* __restrict__ out) {
    int t = blockIdx.x;
    int h = threadIdx.x * 4;
    int p0 = g_pos[2 * t], p1 = g_pos[2 * t + 1];
    float w0 = g_perm_w[p0], w1 = g_perm_w[p1];
    float4 a = *(const float4*)&g_y[(size_t)p0 * HDIM + h];
    float4 b = *(const float4*)&g_y[(size_t)p1 * HDIM + h];
    float4 o;
    o.x = w0 * a.x + w1 * b.x;
    o.y = w0 * a.y + w1 * b.y;
    o.z = w0 * a.z + w1 * b.z;
    o.w = w0 * a.w + w1 * b.w;
    *(float4*)(out + (size_t)t * HDIM + h) = o;
}

// ---------------- launcher (no device-global symbols passed as args) ----------------
extern "C" void kernel_launch(void* const* d_in, const int* in_sizes, int n_in,
                              void* d_out, int out_size) {
    (void)in_sizes; (void)n_in;
    const float* x  = (const float*)d_in[0];
    const float* gw = (const float*)d_in[1];
    const float* wg = (const float*)d_in[2];
    const float* wu = (const float*)d_in[3];
    const float* wd = (const float*)d_in[4];
    float* out = (float*)d_out;

    int write_logits = (out_size >= T_TOK * HDIM + T_TOK * NEXP) ? 1 : 0;

    k_init<<<1, 32>>>();
    k_router<<<T_TOK / 8, 256>>>(x, gw, out + (size_t)T_TOK * HDIM, write_logits);
    k_scan<<<1, 1>>>();
    k_scatter<<<T_TOK / 256, 256>>>();
    k_gather<<<NASSIGN, 256>>>(x);
    // weight prep (hi/lo split + transpose to [E][N][K])
    k_transpose<0><<<dim3(IDIM / 32, HDIM / 32, NEXP), dim3(32, 8)>>>(wg);
    k_transpose<1><<<dim3(IDIM / 32, HDIM / 32, NEXP), dim3(32, 8)>>>(wu);
    k_transpose<2><<<dim3(HDIM / 32, IDIM / 32, NEXP), dim3(32, 8)>>>(wd);
    // fused gate+up GEMM (R11 geometry) with SwiGLU epilogue, then down GEMM
    k_gemm1f<<<dim3(40, IDIM / 32), 256>>>();
    k_gemm2<<<dim3(40, HDIM / 64), 256>>>();
    k_combine<<<T_TOK, 256>>>(out);
}

// round 16
// speedup vs baseline: 2.9587x; 1.3219x over previous
#include <cuda_runtime.h>
#include <cuda_fp16.h>
#include <math.h>
#include <stdint.h>

// ---------------- problem dims (fixed) ----------------
#define T_TOK  2048
#define HDIM   1024
#define IDIM   2816
#define NEXP   8
#define NASSIGN 4096
#define NTMAX  48
#define APAD   (NASSIGN + 128)
#define WELEMS (NEXP * HDIM * IDIM)

// ---------------- device scratch (static globals, allowed) ----------------
__device__ __half g_xg_hi[APAD * HDIM];
__device__ __half g_xg_lo[APAD * HDIM];
__device__ __half g_act_hi[(size_t)APAD * IDIM];
__device__ __half g_act_lo[(size_t)APAD * IDIM];
__device__ float  g_y[(size_t)APAD * HDIM];
__device__ __half g_wgt[WELEMS];   // w_gate^T [E][I][H] fp16
__device__ __half g_wut[WELEMS];   // w_up^T   [E][I][H] fp16
__device__ __half g_wdt[WELEMS];   // w_down^T [E][H][I] fp16

__device__ int   g_perm_tok[NASSIGN];
__device__ float g_perm_w[NASSIGN];
__device__ int   g_pos[NASSIGN];
__device__ int   g_tok_eid[NASSIGN];
__device__ float g_tok_w[NASSIGN];
__device__ int   g_counts[NEXP];
__device__ int   g_off[NEXP + 1];
__device__ int   g_cursor[NEXP];
__device__ int   g_te[NTMAX], g_tr0[NTMAX];
__device__ int   g_nt;

// ---------------- PTX helpers (portable sm_80+ subset) ----------------
__device__ __forceinline__ uint32_t smem_u32(const void* p) {
    uint32_t a;
    asm("{ .reg .u64 t; cvta.to.shared.u64 t, %1; cvt.u32.u64 %0, t; }" : "=r"(a) : "l"(p));
    return a;
}
__device__ __forceinline__ void cpasync16(uint32_t dst, const void* src) {
    asm volatile("cp.async.cg.shared.global [%0], [%1], 16;" :: "r"(dst), "l"(src));
}
__device__ __forceinline__ void cp_commit() {
    asm volatile("cp.async.commit_group;" ::: "memory");
}
__device__ __forceinline__ void cp_wait1() {
    asm volatile("cp.async.wait_group 1;" ::: "memory");
}
__device__ __forceinline__ void ldsm4(uint32_t* r, uint32_t a) {
    asm volatile("ldmatrix.sync.aligned.m8n8.x4.shared.b16 {%0,%1,%2,%3}, [%4];"
                 : "=r"(r[0]), "=r"(r[1]), "=r"(r[2]), "=r"(r[3]) : "r"(a));
}
__device__ __forceinline__ void mma16816h(float* c, const uint32_t* a, uint32_t b0, uint32_t b1) {
    asm volatile(
        "mma.sync.aligned.m16n8k16.row.col.f32.f16.f16.f32 "
        "{%0,%1,%2,%3}, {%4,%5,%6,%7}, {%8,%9}, {%0,%1,%2,%3};"
        : "+f"(c[0]), "+f"(c[1]), "+f"(c[2]), "+f"(c[3])
        : "r"(a[0]), "r"(a[1]), "r"(a[2]), "r"(a[3]), "r"(b0), "r"(b1));
}
// 64B rows (KC=32 fp16), 4x16B chunks, XOR swizzle ch ^= (row>>1)&3 (R11-proven)
__device__ __forceinline__ uint32_t swz64(int row, int ch) {
    return (uint32_t)(row * 64 + (((ch ^ ((row >> 1) & 3)) & 3) << 4));
}

// ---------------- small kernels ----------------
__global__ void k_init() {
    int i = threadIdx.x;
    if (i < NEXP) { g_counts[i] = 0; g_cursor[i] = 0; }
}

__global__ void k_router(const float* __restrict__ x, const float* __restrict__ gw,
                         float* __restrict__ out_logits, int write_logits) {
    int warp = threadIdx.x >> 5, lane = threadIdx.x & 31;
    int t = blockIdx.x * 8 + warp;
    const float* xt = x + (size_t)t * HDIM;
    float xr[32];
#pragma unroll
    for (int i = 0; i < 32; i++) xr[i] = xt[i * 32 + lane];
    float lg[NEXP];
#pragma unroll
    for (int e = 0; e < NEXP; e++) {
        const float* ge = gw + e * HDIM;
        float s = 0.f;
#pragma unroll
        for (int i = 0; i < 32; i++) s += xr[i] * ge[i * 32 + lane];
#pragma unroll
        for (int o = 16; o > 0; o >>= 1) s += __shfl_xor_sync(0xffffffffu, s, o);
        lg[e] = s;
    }
    if (lane == 0) {
        if (write_logits) {
#pragma unroll
            for (int e = 0; e < NEXP; e++) out_logits[t * NEXP + e] = lg[e];
        }
        int a = 0;
#pragma unroll
        for (int e = 1; e < NEXP; e++) if (lg[e] > lg[a]) a = e;
        int b = (a == 0) ? 1 : 0;
#pragma unroll
        for (int e = 0; e < NEXP; e++) if (e != a && lg[e] > lg[b]) b = e;
        float wa = 1.f / (1.f + expf(lg[b] - lg[a]));
        g_tok_eid[2 * t]     = a; g_tok_w[2 * t]     = wa;
        g_tok_eid[2 * t + 1] = b; g_tok_w[2 * t + 1] = 1.f - wa;
        atomicAdd(&g_counts[a], 1);
        atomicAdd(&g_counts[b], 1);
    }
}

__global__ void k_scan() {
    if (threadIdx.x != 0) return;
    int off = 0;
    for (int e = 0; e < NEXP; e++) { g_off[e] = off; g_cursor[e] = off; off += g_counts[e]; }
    g_off[NEXP] = off;
    int nt = 0;
    for (int e = 0; e < NEXP; e++)
        for (int r = 0; r < g_counts[e]; r += 128) { g_te[nt] = e; g_tr0[nt] = g_off[e] + r; nt++; }
    g_nt = nt;
}

__global__ void k_scatter() {
    int t = blockIdx.x * blockDim.x + threadIdx.x;
    if (t >= T_TOK) return;
#pragma unroll
    for (int k = 0; k < 2; k++) {
        int e = g_tok_eid[2 * t + k];
        int pos = atomicAdd(&g_cursor[e], 1);
        g_perm_tok[pos] = t;
        g_perm_w[pos]   = g_tok_w[2 * t + k];
        g_pos[2 * t + k] = pos;
    }
}

// gather token rows, fp32 -> fp16 hi + fp16 lo (A is fp32-accurate via 2 digits)
__global__ void k_gather(const float* __restrict__ x) {
    int pos = blockIdx.x;
    int tok = g_perm_tok[pos];
    int i = threadIdx.x * 4;
    float4 v = *(const float4*)(x + (size_t)tok * HDIM + i);
    size_t o = (size_t)pos * HDIM + i;
    float vv[4] = { v.x, v.y, v.z, v.w };
#pragma unroll
    for (int j = 0; j < 4; j++) {
        __half h = __float2half_rn(vv[j]);
        g_xg_hi[o + j] = h;
        g_xg_lo[o + j] = __float2half_rn(vv[j] - __half2float(h));
    }
}

// transpose W[e][K][N] fp32 -> single fp16 [e][N][K]
template<int SEL>
__global__ void k_transpose(const float* __restrict__ W) {
    constexpr int K = (SEL == 2) ? IDIM : HDIM;
    constexpr int N = (SEL == 2) ? HDIM : IDIM;
    __half* dst = (SEL == 0) ? g_wgt : (SEL == 1) ? g_wut : g_wdt;

    __shared__ float tile[32][33];
    int e = blockIdx.z;
    const float* We = W + (size_t)e * K * N;
    size_t ob = (size_t)e * K * N;
    int n0 = blockIdx.x * 32, k0 = blockIdx.y * 32;
    int tx = threadIdx.x, ty = threadIdx.y;
#pragma unroll
    for (int i = 0; i < 4; i++)
        tile[ty * 4 + i][tx] = We[(size_t)(k0 + ty * 4 + i) * N + n0 + tx];
    __syncthreads();
#pragma unroll
    for (int i = 0; i < 4; i++) {
        int r = ty * 4 + i;
        dst[ob + (size_t)(n0 + r) * K + k0 + tx] = __float2half_rn(tile[tx][r]);
    }
}

// ======= GEMM1 fused: G,U = X@Wg^T,X@Wu^T; fp16 2-term; SwiGLU epilogue ===========
// BM=128, BN=32 (G) + 32 (U), KC=32, 2-stage cp.async, 40KB static smem.
// stage (20KB): [Ah 8K | Al 8K | G 2K | U 2K]
#define F_A1 0
#define F_A2 8192
#define F_G  16384
#define F_U  18432
#define F_SZ 20480

__global__ __launch_bounds__(256)
void k_gemm1f() {
    constexpr int NCH = HDIM / 32;   // 32 chunks
    __shared__ __align__(16) char smem[2 * F_SZ];

    int bx = blockIdx.x;
    if (bx >= g_nt) return;
    int e = g_te[bx], row0 = g_tr0[bx], send = g_off[e + 1];
    int nblk = blockIdx.y * 32;
    int tid = threadIdx.x, lane = tid & 31, warp = tid >> 5;
    int wm = (warp >> 1) * 32, wn16 = (warp & 1) * 16;   // 4M x 2N warps

    const __half* pa_h = g_xg_hi + (size_t)row0 * HDIM;
    const __half* pa_l = g_xg_lo + (size_t)row0 * HDIM;
    size_t eoff = ((size_t)e * IDIM + nblk) * HDIM;
    const __half* pg = g_wgt + eoff;
    const __half* pu = g_wut + eoff;

    uint32_t sb = smem_u32(smem);

    auto issue = [&](int c) {
        if (c < NCH) {
            int k0 = c << 5;
            uint32_t b = sb + (uint32_t)(c & 1) * F_SZ;
#pragma unroll
            for (int r = 0; r < 2; r++) {          // A: 128 rows x 4 chunks, hi+lo
                int idx = r * 256 + tid;
                int row = idx >> 2, ch = idx & 3;
                uint32_t sw = swz64(row, ch);
                size_t go = (size_t)row * HDIM + k0 + ch * 8;
                cpasync16(b + F_A1 + sw, pa_h + go);
                cpasync16(b + F_A2 + sw, pa_l + go);
            }
            {                                       // B: 2 regions x 32 rows x 4 chunks
                int reg = tid >> 7, within = tid & 127;
                int row = within >> 2, ch = within & 3;
                uint32_t sw = swz64(row, ch);
                size_t go = (size_t)row * HDIM + k0 + ch * 8;
                const __half* src = reg ? pu : pg;
                cpasync16(b + F_G + reg * 2048 + sw, src + go);
            }
        }
        cp_commit();
    };

    issue(0);
    issue(1);

    float ag[2][2][4], au[2][2][4];
#pragma unroll
    for (int i = 0; i < 2; i++)
#pragma unroll
        for (int j = 0; j < 2; j++)
#pragma unroll
            for (int k = 0; k < 4; k++) { ag[i][j][k] = 0.f; au[i][j][k] = 0.f; }

    int lrow = lane & 15, lch = lane >> 4;

    for (int c = 0; c < NCH; c++) {
        cp_wait1();
        __syncthreads();
        uint32_t base = sb + (uint32_t)(c & 1) * F_SZ;
#pragma unroll
        for (int s = 0; s < 2; s++) {              // two k16 steps per 32-chunk
            int ch = 2 * s + lch;
            uint32_t ah[2][4], al[2][4];
#pragma unroll
            for (int mt = 0; mt < 2; mt++) {
                uint32_t sw = swz64(wm + mt * 16 + lrow, ch);
                ldsm4(ah[mt], base + F_A1 + sw);
                ldsm4(al[mt], base + F_A2 + sw);
            }
            uint32_t swb = swz64(wn16 + lrow, ch);
            uint32_t bg[4], bu[4];
            ldsm4(bg, base + F_G + swb);
            ldsm4(bu, base + F_U + swb);
#pragma unroll
            for (int nh = 0; nh < 2; nh++) {
#pragma unroll
                for (int mt = 0; mt < 2; mt++) {
                    mma16816h(ag[mt][nh], ah[mt], bg[nh], bg[nh + 2]);
                    mma16816h(ag[mt][nh], al[mt], bg[nh], bg[nh + 2]);
                    mma16816h(au[mt][nh], ah[mt], bu[nh], bu[nh + 2]);
                    mma16816h(au[mt][nh], al[mt], bu[nh], bu[nh + 2]);
                }
            }
        }
        __syncthreads();
        issue(c + 2);
    }

    // fused SwiGLU epilogue: act = silu(g)*u -> fp16 hi/lo
    int r_off = lane >> 2, c_off = (lane & 3) * 2;
#pragma unroll
    for (int mt = 0; mt < 2; mt++) {
#pragma unroll
        for (int h = 0; h < 2; h++) {
            int row = row0 + wm + mt * 16 + r_off + h * 8;
            if (row >= send) continue;
#pragma unroll
            for (int nh = 0; nh < 2; nh++) {
                float g0 = ag[mt][nh][2 * h + 0], g1 = ag[mt][nh][2 * h + 1];
                float u0 = au[mt][nh][2 * h + 0], u1 = au[mt][nh][2 * h + 1];
                float a0 = g0 * u0 / (1.f + __expf(-g0));
                float a1 = g1 * u1 / (1.f + __expf(-g1));
                __half h0 = __float2half_rn(a0);
                __half h1 = __float2half_rn(a1);
                __half l0 = __float2half_rn(a0 - __half2float(h0));
                __half l1 = __float2half_rn(a1 - __half2float(h1));
                size_t o = (size_t)row * IDIM + nblk + wn16 + nh * 8 + c_off;
                *reinterpret_cast<__half2*>(&g_act_hi[o]) = __halves2half2(h0, h1);
                *reinterpret_cast<__half2*>(&g_act_lo[o]) = __halves2half2(l0, l1);
            }
        }
    }
}

// ======= GEMM2: Y = act@Wd^T  (fp16 2-term, BM=128, BN=64, KC=32, 2-stage) =========
// stage (20KB): [Ah 8K | Al 8K | B 4K]
#define D_A1 0
#define D_A2 8192
#define D_B  16384
#define D_SZ 20480

__global__ __launch_bounds__(256)
void k_gemm2() {
    constexpr int Kd = IDIM, Nd = HDIM;
    constexpr int NCH = Kd / 32;
    __shared__ __align__(16) char smem[2 * D_SZ];

    int bx = blockIdx.x;
    if (bx >= g_nt) return;
    int e = g_te[bx], row0 = g_tr0[bx], send = g_off[e + 1];
    int nblk = blockIdx.y * 64;
    int tid = threadIdx.x, lane = tid & 31, warp = tid >> 5;
    int wm = (warp >> 1) * 32, wn = (warp & 1) * 32;

    const __half* pa_h = g_act_hi + (size_t)row0 * Kd;
    const __half* pa_l = g_act_lo + (size_t)row0 * Kd;
    const __half* pb = g_wdt + ((size_t)e * Nd + nblk) * Kd;

    uint32_t sb = smem_u32(smem);

    auto issue = [&](int c) {
        if (c < NCH) {
            int k0 = c << 5;
            uint32_t b = sb + (uint32_t)(c & 1) * D_SZ;
#pragma unroll
            for (int r = 0; r < 2; r++) {
                int idx = r * 256 + tid;
                int row = idx >> 2, ch = idx & 3;
                uint32_t sw = swz64(row, ch);
                size_t go = (size_t)row * Kd + k0 + ch * 8;
                cpasync16(b + D_A1 + sw, pa_h + go);
                cpasync16(b + D_A2 + sw, pa_l + go);
            }
            {
                int row = tid >> 2, ch = tid & 3;   // 64 rows x 4 chunks
                uint32_t sw = swz64(row, ch);
                size_t go = (size_t)row * Kd + k0 + ch * 8;
                cpasync16(b + D_B + sw, pb + go);
            }
        }
        cp_commit();
    };

    issue(0);
    issue(1);

    float acc[2][4][4];
#pragma unroll
    for (int i = 0; i < 2; i++)
#pragma unroll
        for (int j = 0; j < 4; j++)
#pragma unroll
            for (int k = 0; k < 4; k++) acc[i][j][k] = 0.f;

    int lrow = lane & 15, lch = lane >> 4;

    for (int c = 0; c < NCH; c++) {
        cp_wait1();
        __syncthreads();
        uint32_t base = sb + (uint32_t)(c & 1) * D_SZ;
#pragma unroll
        for (int s = 0; s < 2; s++) {
            int ch = 2 * s + lch;
            uint32_t ah[2][4], al[2][4];
#pragma unroll
            for (int mt = 0; mt < 2; mt++) {
                uint32_t sw = swz64(wm + mt * 16 + lrow, ch);
                ldsm4(ah[mt], base + D_A1 + sw);
                ldsm4(al[mt], base + D_A2 + sw);
            }
#pragma unroll
            for (int p = 0; p < 2; p++) {
                uint32_t sw = swz64(wn + p * 16 + lrow, ch);
                uint32_t bb[4];
                ldsm4(bb, base + D_B + sw);
#pragma unroll
                for (int mt = 0; mt < 2; mt++) {
                    mma16816h(acc[mt][2 * p],     ah[mt], bb[0], bb[2]);
                    mma16816h(acc[mt][2 * p],     al[mt], bb[0], bb[2]);
                    mma16816h(acc[mt][2 * p + 1], ah[mt], bb[1], bb[3]);
                    mma16816h(acc[mt][2 * p + 1], al[mt], bb[1], bb[3]);
                }
            }
        }
        __syncthreads();
        issue(c + 2);
    }

    int r_off = lane >> 2, c_off = (lane & 3) * 2;
#pragma unroll
    for (int mt = 0; mt < 2; mt++) {
#pragma unroll
        for (int h = 0; h < 2; h++) {
            int row = row0 + wm + mt * 16 + r_off + h * 8;
            if (row >= send) continue;
            float* crow = g_y + (size_t)row * Nd + nblk + wn + c_off;
#pragma unroll
            for (int nt = 0; nt < 4; nt++) {
                crow[nt * 8 + 0] = acc[mt][nt][2 * h + 0];
                crow[nt * 8 + 1] = acc[mt][nt][2 * h + 1];
            }
        }
    }
}

// ---------------- combine: out[t] = w0*y[p0] + w1*y[p1] ----------------
__global__ void k_combine(float* __restrict__ out) {
    int t = blockIdx.x;
    int h = threadIdx.x * 4;
    int p0 = g_pos[2 * t], p1 = g_pos[2 * t + 1];
    float w0 = g_perm_w[p0], w1 = g_perm_w[p1];
    float4 a = *(const float4*)&g_y[(size_t)p0 * HDIM + h];
    float4 b = *(const float4*)&g_y[(size_t)p1 * HDIM + h];
    float4 o;
    o.x = w0 * a.x + w1 * b.x;
    o.y = w0 * a.y + w1 * b.y;
    o.z = w0 * a.z + w1 * b.z;
    o.w = w0 * a.w + w1 * b.w;
    *(float4*)(out + (size_t)t * HDIM + h) = o;
}

// ---------------- launcher (no device-global symbols passed as args) ----------------
extern "C" void kernel_launch(void* const* d_in, const int* in_sizes, int n_in,
                              void* d_out, int out_size) {
    (void)in_sizes; (void)n_in;
    const float* x  = (const float*)d_in[0];
    const float* gw = (const float*)d_in[1];
    const float* wg = (const float*)d_in[2];
    const float* wu = (const float*)d_in[3];
    const float* wd = (const float*)d_in[4];
    float* out = (float*)d_out;

    int write_logits = (out_size >= T_TOK * HDIM + T_TOK * NEXP) ? 1 : 0;

    k_init<<<1, 32>>>();
    k_router<<<T_TOK / 8, 256>>>(x, gw, out + (size_t)T_TOK * HDIM, write_logits);
    k_scan<<<1, 1>>>();
    k_scatter<<<T_TOK / 256, 256>>>();
    k_gather<<<NASSIGN, 256>>>(x);
    // weight prep (single fp16 + transpose to [E][N][K])
    k_transpose<0><<<dim3(IDIM / 32, HDIM / 32, NEXP), dim3(32, 8)>>>(wg);
    k_transpose<1><<<dim3(IDIM / 32, HDIM / 32, NEXP), dim3(32, 8)>>>(wu);
    k_transpose<2><<<dim3(HDIM / 32, IDIM / 32, NEXP), dim3(32, 8)>>>(wd);
    // fp16 2-term grouped GEMMs (2/3 the mma instructions of bf16 split-3)
    k_gemm1f<<<dim3(40, IDIM / 32), 256>>>();
    k_gemm2<<<dim3(40, HDIM / 64), 256>>>();
    k_combine<<<T_TOK, 256>>>(out);
}

// round 17
// speedup vs baseline: 4.7381x; 1.6014x over previous
#include <cuda_runtime.h>
#include <cuda_fp16.h>
#include <math.h>
#include <stdint.h>

// ---------------- problem dims (fixed) ----------------
#define T_TOK  2048
#define HDIM   1024
#define IDIM   2816
#define NEXP   8
#define NASSIGN 4096
#define NTMAX  48
#define APAD   (NASSIGN + 128)
#define WELEMS (NEXP * HDIM * IDIM)

// ---------------- device scratch (static globals, allowed) ----------------
__device__ __half g_xg[APAD * HDIM];                 // gathered X fp16
__device__ __half g_act[(size_t)APAD * IDIM];        // SwiGLU activations fp16
__device__ float  g_y[(size_t)APAD * HDIM];
__device__ __half g_wgt[WELEMS];   // w_gate^T [E][I][H] fp16
__device__ __half g_wut[WELEMS];   // w_up^T   [E][I][H] fp16
__device__ __half g_wdt[WELEMS];   // w_down^T [E][H][I] fp16

__device__ int   g_perm_tok[NASSIGN];
__device__ float g_perm_w[NASSIGN];
__device__ int   g_pos[NASSIGN];
__device__ int   g_tok_eid[NASSIGN];
__device__ float g_tok_w[NASSIGN];
__device__ int   g_counts[NEXP];
__device__ int   g_off[NEXP + 1];
__device__ int   g_cursor[NEXP];
__device__ int   g_te[NTMAX], g_tr0[NTMAX];
__device__ int   g_nt;

// ---------------- PTX helpers (portable sm_80+ subset) ----------------
__device__ __forceinline__ uint32_t smem_u32(const void* p) {
    uint32_t a;
    asm("{ .reg .u64 t; cvta.to.shared.u64 t, %1; cvt.u32.u64 %0, t; }" : "=r"(a) : "l"(p));
    return a;
}
__device__ __forceinline__ void cpasync16(uint32_t dst, const void* src) {
    asm volatile("cp.async.cg.shared.global [%0], [%1], 16;" :: "r"(dst), "l"(src));
}
__device__ __forceinline__ void cp_commit() {
    asm volatile("cp.async.commit_group;" ::: "memory");
}
__device__ __forceinline__ void cp_wait1() {
    asm volatile("cp.async.wait_group 1;" ::: "memory");
}
__device__ __forceinline__ void ldsm4(uint32_t* r, uint32_t a) {
    asm volatile("ldmatrix.sync.aligned.m8n8.x4.shared.b16 {%0,%1,%2,%3}, [%4];"
                 : "=r"(r[0]), "=r"(r[1]), "=r"(r[2]), "=r"(r[3]) : "r"(a));
}
__device__ __forceinline__ void mma16816h(float* c, const uint32_t* a, uint32_t b0, uint32_t b1) {
    asm volatile(
        "mma.sync.aligned.m16n8k16.row.col.f32.f16.f16.f32 "
        "{%0,%1,%2,%3}, {%4,%5,%6,%7}, {%8,%9}, {%0,%1,%2,%3};"
        : "+f"(c[0]), "+f"(c[1]), "+f"(c[2]), "+f"(c[3])
        : "r"(a[0]), "r"(a[1]), "r"(a[2]), "r"(a[3]), "r"(b0), "r"(b1));
}
// 64B rows (KC=32 fp16), 4x16B chunks, XOR swizzle ch ^= (row>>1)&3 (R11-proven)
__device__ __forceinline__ uint32_t swz64(int row, int ch) {
    return (uint32_t)(row * 64 + (((ch ^ ((row >> 1) & 3)) & 3) << 4));
}

// ---------------- small kernels ----------------
__global__ void k_init() {
    int i = threadIdx.x;
    if (i < NEXP) { g_counts[i] = 0; g_cursor[i] = 0; }
}

__global__ void k_router(const float* __restrict__ x, const float* __restrict__ gw,
                         float* __restrict__ out_logits, int write_logits) {
    int warp = threadIdx.x >> 5, lane = threadIdx.x & 31;
    int t = blockIdx.x * 8 + warp;
    const float* xt = x + (size_t)t * HDIM;
    float xr[32];
#pragma unroll
    for (int i = 0; i < 32; i++) xr[i] = xt[i * 32 + lane];
    float lg[NEXP];
#pragma unroll
    for (int e = 0; e < NEXP; e++) {
        const float* ge = gw + e * HDIM;
        float s = 0.f;
#pragma unroll
        for (int i = 0; i < 32; i++) s += xr[i] * ge[i * 32 + lane];
#pragma unroll
        for (int o = 16; o > 0; o >>= 1) s += __shfl_xor_sync(0xffffffffu, s, o);
        lg[e] = s;
    }
    if (lane == 0) {
        if (write_logits) {
#pragma unroll
            for (int e = 0; e < NEXP; e++) out_logits[t * NEXP + e] = lg[e];
        }
        int a = 0;
#pragma unroll
        for (int e = 1; e < NEXP; e++) if (lg[e] > lg[a]) a = e;
        int b = (a == 0) ? 1 : 0;
#pragma unroll
        for (int e = 0; e < NEXP; e++) if (e != a && lg[e] > lg[b]) b = e;
        float wa = 1.f / (1.f + expf(lg[b] - lg[a]));
        g_tok_eid[2 * t]     = a; g_tok_w[2 * t]     = wa;
        g_tok_eid[2 * t + 1] = b; g_tok_w[2 * t + 1] = 1.f - wa;
        atomicAdd(&g_counts[a], 1);
        atomicAdd(&g_counts[b], 1);
    }
}

__global__ void k_scan() {
    if (threadIdx.x != 0) return;
    int off = 0;
    for (int e = 0; e < NEXP; e++) { g_off[e] = off; g_cursor[e] = off; off += g_counts[e]; }
    g_off[NEXP] = off;
    int nt = 0;
    for (int e = 0; e < NEXP; e++)
        for (int r = 0; r < g_counts[e]; r += 128) { g_te[nt] = e; g_tr0[nt] = g_off[e] + r; nt++; }
    g_nt = nt;
}

__global__ void k_scatter() {
    int t = blockIdx.x * blockDim.x + threadIdx.x;
    if (t >= T_TOK) return;
#pragma unroll
    for (int k = 0; k < 2; k++) {
        int e = g_tok_eid[2 * t + k];
        int pos = atomicAdd(&g_cursor[e], 1);
        g_perm_tok[pos] = t;
        g_perm_w[pos]   = g_tok_w[2 * t + k];
        g_pos[2 * t + k] = pos;
    }
}

// gather token rows, fp32 -> fp16
__global__ void k_gather(const float* __restrict__ x) {
    int pos = blockIdx.x;
    int tok = g_perm_tok[pos];
    int i = threadIdx.x * 4;
    float4 v = *(const float4*)(x + (size_t)tok * HDIM + i);
    size_t o = (size_t)pos * HDIM + i;
    g_xg[o + 0] = __float2half_rn(v.x);
    g_xg[o + 1] = __float2half_rn(v.y);
    g_xg[o + 2] = __float2half_rn(v.z);
    g_xg[o + 3] = __float2half_rn(v.w);
}

// transpose W[e][K][N] fp32 -> single fp16 [e][N][K]
template<int SEL>
__global__ void k_transpose(const float* __restrict__ W) {
    constexpr int K = (SEL == 2) ? IDIM : HDIM;
    constexpr int N = (SEL == 2) ? HDIM : IDIM;
    __half* dst = (SEL == 0) ? g_wgt : (SEL == 1) ? g_wut : g_wdt;

    __shared__ float tile[32][33];
    int e = blockIdx.z;
    const float* We = W + (size_t)e * K * N;
    size_t ob = (size_t)e * K * N;
    int n0 = blockIdx.x * 32, k0 = blockIdx.y * 32;
    int tx = threadIdx.x, ty = threadIdx.y;
#pragma unroll
    for (int i = 0; i < 4; i++)
        tile[ty * 4 + i][tx] = We[(size_t)(k0 + ty * 4 + i) * N + n0 + tx];
    __syncthreads();
#pragma unroll
    for (int i = 0; i < 4; i++) {
        int r = ty * 4 + i;
        dst[ob + (size_t)(n0 + r) * K + k0 + tx] = __float2half_rn(tile[tx][r]);
    }
}

// ======= GEMM1 fused: G,U = X@Wg^T,X@Wu^T; single fp16; SwiGLU epilogue ===========
// BM=128, BN=32 (G) + 32 (U), KC=32, 2-stage cp.async, 24KB static smem.
// stage (12KB): [A 8K | G 2K | U 2K]
#define F_A  0
#define F_G  8192
#define F_U  10240
#define F_SZ 12288

__global__ __launch_bounds__(256)
void k_gemm1f() {
    constexpr int NCH = HDIM / 32;   // 32 chunks
    __shared__ __align__(16) char smem[2 * F_SZ];

    int bx = blockIdx.x;
    if (bx >= g_nt) return;
    int e = g_te[bx], row0 = g_tr0[bx], send = g_off[e + 1];
    int nblk = blockIdx.y * 32;
    int tid = threadIdx.x, lane = tid & 31, warp = tid >> 5;
    int wm = (warp >> 1) * 32, wn16 = (warp & 1) * 16;   // 4M x 2N warps

    const __half* pa = g_xg + (size_t)row0 * HDIM;
    size_t eoff = ((size_t)e * IDIM + nblk) * HDIM;
    const __half* pg = g_wgt + eoff;
    const __half* pu = g_wut + eoff;

    uint32_t sb = smem_u32(smem);

    auto issue = [&](int c) {
        if (c < NCH) {
            int k0 = c << 5;
            uint32_t b = sb + (uint32_t)(c & 1) * F_SZ;
#pragma unroll
            for (int r = 0; r < 2; r++) {          // A: 128 rows x 4 chunks
                int idx = r * 256 + tid;
                int row = idx >> 2, ch = idx & 3;
                uint32_t sw = swz64(row, ch);
                cpasync16(b + F_A + sw, pa + (size_t)row * HDIM + k0 + ch * 8);
            }
            {                                       // B: 2 regions x 32 rows x 4 chunks
                int reg = tid >> 7, within = tid & 127;
                int row = within >> 2, ch = within & 3;
                uint32_t sw = swz64(row, ch);
                size_t go = (size_t)row * HDIM + k0 + ch * 8;
                const __half* src = reg ? pu : pg;
                cpasync16(b + F_G + reg * 2048 + sw, src + go);
            }
        }
        cp_commit();
    };

    issue(0);
    issue(1);

    float ag[2][2][4], au[2][2][4];
#pragma unroll
    for (int i = 0; i < 2; i++)
#pragma unroll
        for (int j = 0; j < 2; j++)
#pragma unroll
            for (int k = 0; k < 4; k++) { ag[i][j][k] = 0.f; au[i][j][k] = 0.f; }

    int lrow = lane & 15, lch = lane >> 4;

    for (int c = 0; c < NCH; c++) {
        cp_wait1();
        __syncthreads();
        uint32_t base = sb + (uint32_t)(c & 1) * F_SZ;
#pragma unroll
        for (int s = 0; s < 2; s++) {              // two k16 steps per 32-chunk
            int ch = 2 * s + lch;
            uint32_t ah[2][4];
#pragma unroll
            for (int mt = 0; mt < 2; mt++) {
                uint32_t sw = swz64(wm + mt * 16 + lrow, ch);
                ldsm4(ah[mt], base + F_A + sw);
            }
            uint32_t swb = swz64(wn16 + lrow, ch);
            uint32_t bg[4], bu[4];
            ldsm4(bg, base + F_G + swb);
            ldsm4(bu, base + F_U + swb);
#pragma unroll
            for (int nh = 0; nh < 2; nh++) {
#pragma unroll
                for (int mt = 0; mt < 2; mt++) {
                    mma16816h(ag[mt][nh], ah[mt], bg[nh], bg[nh + 2]);
                    mma16816h(au[mt][nh], ah[mt], bu[nh], bu[nh + 2]);
                }
            }
        }
        __syncthreads();
        issue(c + 2);
    }

    // fused SwiGLU epilogue: act = silu(g)*u -> fp16
    int r_off = lane >> 2, c_off = (lane & 3) * 2;
#pragma unroll
    for (int mt = 0; mt < 2; mt++) {
#pragma unroll
        for (int h = 0; h < 2; h++) {
            int row = row0 + wm + mt * 16 + r_off + h * 8;
            if (row >= send) continue;
#pragma unroll
            for (int nh = 0; nh < 2; nh++) {
                float g0 = ag[mt][nh][2 * h + 0], g1 = ag[mt][nh][2 * h + 1];
                float u0 = au[mt][nh][2 * h + 0], u1 = au[mt][nh][2 * h + 1];
                float a0 = g0 * u0 / (1.f + __expf(-g0));
                float a1 = g1 * u1 / (1.f + __expf(-g1));
                size_t o = (size_t)row * IDIM + nblk + wn16 + nh * 8 + c_off;
                *reinterpret_cast<__half2*>(&g_act[o]) =
                    __halves2half2(__float2half_rn(a0), __float2half_rn(a1));
            }
        }
    }
}

// ======= GEMM2: Y = act@Wd^T  (single fp16, BM=128, BN=64, KC=32, 2-stage) =========
// stage (12KB): [A 8K | B 4K]
#define D_A  0
#define D_B  8192
#define D_SZ 12288

__global__ __launch_bounds__(256)
void k_gemm2() {
    constexpr int Kd = IDIM, Nd = HDIM;
    constexpr int NCH = Kd / 32;
    __shared__ __align__(16) char smem[2 * D_SZ];

    int bx = blockIdx.x;
    if (bx >= g_nt) return;
    int e = g_te[bx], row0 = g_tr0[bx], send = g_off[e + 1];
    int nblk = blockIdx.y * 64;
    int tid = threadIdx.x, lane = tid & 31, warp = tid >> 5;
    int wm = (warp >> 1) * 32, wn = (warp & 1) * 32;

    const __half* pa = g_act + (size_t)row0 * Kd;
    const __half* pb = g_wdt + ((size_t)e * Nd + nblk) * Kd;

    uint32_t sb = smem_u32(smem);

    auto issue = [&](int c) {
        if (c < NCH) {
            int k0 = c << 5;
            uint32_t b = sb + (uint32_t)(c & 1) * D_SZ;
#pragma unroll
            for (int r = 0; r < 2; r++) {          // A: 128 rows x 4 chunks
                int idx = r * 256 + tid;
                int row = idx >> 2, ch = idx & 3;
                uint32_t sw = swz64(row, ch);
                cpasync16(b + D_A + sw, pa + (size_t)row * Kd + k0 + ch * 8);
            }
            {
                int row = tid >> 2, ch = tid & 3;   // B: 64 rows x 4 chunks
                uint32_t sw = swz64(row, ch);
                cpasync16(b + D_B + sw, pb + (size_t)row * Kd + k0 + ch * 8);
            }
        }
        cp_commit();
    };

    issue(0);
    issue(1);

    float acc[2][4][4];
#pragma unroll
    for (int i = 0; i < 2; i++)
#pragma unroll
        for (int j = 0; j < 4; j++)
#pragma unroll
            for (int k = 0; k < 4; k++) acc[i][j][k] = 0.f;

    int lrow = lane & 15, lch = lane >> 4;

    for (int c = 0; c < NCH; c++) {
        cp_wait1();
        __syncthreads();
        uint32_t base = sb + (uint32_t)(c & 1) * D_SZ;
#pragma unroll
        for (int s = 0; s < 2; s++) {
            int ch = 2 * s + lch;
            uint32_t ah[2][4];
#pragma unroll
            for (int mt = 0; mt < 2; mt++) {
                uint32_t sw = swz64(wm + mt * 16 + lrow, ch);
                ldsm4(ah[mt], base + D_A + sw);
            }
#pragma unroll
            for (int p = 0; p < 2; p++) {
                uint32_t sw = swz64(wn + p * 16 + lrow, ch);
                uint32_t bb[4];
                ldsm4(bb, base + D_B + sw);
#pragma unroll
                for (int mt = 0; mt < 2; mt++) {
                    mma16816h(acc[mt][2 * p],     ah[mt], bb[0], bb[2]);
                    mma16816h(acc[mt][2 * p + 1], ah[mt], bb[1], bb[3]);
                }
            }
        }
        __syncthreads();
        issue(c + 2);
    }

    int r_off = lane >> 2, c_off = (lane & 3) * 2;
#pragma unroll
    for (int mt = 0; mt < 2; mt++) {
#pragma unroll
        for (int h = 0; h < 2; h++) {
            int row = row0 + wm + mt * 16 + r_off + h * 8;
            if (row >= send) continue;
            float* crow = g_y + (size_t)row * Nd + nblk + wn + c_off;
#pragma unroll
            for (int nt = 0; nt < 4; nt++) {
                crow[nt * 8 + 0] = acc[mt][nt][2 * h + 0];
                crow[nt * 8 + 1] = acc[mt][nt][2 * h + 1];
            }
        }
    }
}

// ---------------- combine: out[t] = w0*y[p0] + w1*y[p1] ----------------
__global__ void k_combine(float* __restrict__ out) {
    int t = blockIdx.x;
    int h = threadIdx.x * 4;
    int p0 = g_pos[2 * t], p1 = g_pos[2 * t + 1];
    float w0 = g_perm_w[p0], w1 = g_perm_w[p1];
    float4 a = *(const float4*)&g_y[(size_t)p0 * HDIM + h];
    float4 b = *(const float4*)&g_y[(size_t)p1 * HDIM + h];
    float4 o;
    o.x = w0 * a.x + w1 * b.x;
    o.y = w0 * a.y + w1 * b.y;
    o.z = w0 * a.z + w1 * b.z;
    o.w = w0 * a.w + w1 * b.w;
    *(float4*)(out + (size_t)t * HDIM + h) = o;
}

// ---------------- launcher (no device-global symbols passed as args) ----------------
extern "C" void kernel_launch(void* const* d_in, const int* in_sizes, int n_in,
                              void* d_out, int out_size) {
    (void)in_sizes; (void)n_in;
    const float* x  = (const float*)d_in[0];
    const float* gw = (const float*)d_in[1];
    const float* wg = (const float*)d_in[2];
    const float* wu = (const float*)d_in[3];
    const float* wd = (const float*)d_in[4];
    float* out = (float*)d_out;

    int write_logits = (out_size >= T_TOK * HDIM + T_TOK * NEXP) ? 1 : 0;

    k_init<<<1, 32>>>();
    k_router<<<T_TOK / 8, 256>>>(x, gw, out + (size_t)T_TOK * HDIM, write_logits);
    k_scan<<<1, 1>>>();
    k_scatter<<<T_TOK / 256, 256>>>();
    k_gather<<<NASSIGN, 256>>>(x);
    // weight prep (single fp16 + transpose to [E][N][K])
    k_transpose<0><<<dim3(IDIM / 32, HDIM / 32, NEXP), dim3(32, 8)>>>(wg);
    k_transpose<1><<<dim3(IDIM / 32, HDIM / 32, NEXP), dim3(32, 8)>>>(wu);
    k_transpose<2><<<dim3(HDIM / 32, IDIM / 32, NEXP), dim3(32, 8)>>>(wd);
    // single-term fp16 grouped GEMMs (half the mma instructions of 2-term)
    k_gemm1f<<<dim3(40, IDIM / 32), 256>>>();
    k_gemm2<<<dim3(40, HDIM / 64), 256>>>();
    k_combine<<<T_TOK, 256>>>(out);
}